// round 4
// baseline (speedup 1.0000x reference)
#include <cuda_runtime.h>
#include <cuda_bf16.h>
#include <cstdint>

// CapsuleRoutingPooling, B=16 C=64 H=64 W=64 D=16, k=2.
// softmax over a length-1 axis => c==1 => routing loop is a no-op.
// out = squash( 2x2 sum-pool of D=16 vectors ).
//
// R4: double-buffered 2-unit blocks. R3 hit 79.6% DRAM: each block's loads
// all landed before its single sync, leaving a no-loads-outstanding window
// until block retirement. Here each block processes TWO 16KB units with
// separate smem buffers; unit-1's LDGs are issued before the first sync so
// the DRAM pipe stays fed while unit-0 is computed. Peak MLP/thread 4->8.

static constexpr int NBLOCKS = 16 * 64 * 8;    // 8192 blocks x 2 units each

__device__ __forceinline__ int swz(int idx) {
    // Toggle bit2 of the float4 index by bit3: kills the 2-way LDS.128
    // conflict of the (nw*8+dq, +4) read pattern while keeping the
    // consecutive-index STS conflict-free. Involution, stays in-range.
    return idx ^ ((idx >> 1) & 4);
}

__device__ __forceinline__ void pool_squash_store(
    const float4* __restrict__ sm, float4* __restrict__ out,
    size_t obase, int t)
{
    const int nh_loc = t >> 7;        // 0..1
    const int rem    = t & 127;
    const int nw     = rem >> 2;      // 0..31
    const int dq     = rem & 3;       // 0..3

    const int r = nh_loc * 512 + nw * 8 + dq;
    const float4 a = sm[swz(r)];
    const float4 b = sm[swz(r + 4)];
    const float4 c = sm[swz(r + 256)];
    const float4 d = sm[swz(r + 260)];

    float4 s;
    s.x = (a.x + b.x) + (c.x + d.x);
    s.y = (a.y + b.y) + (c.y + d.y);
    s.z = (a.z + b.z) + (c.z + d.z);
    s.w = (a.w + b.w) + (c.w + d.w);

    float sq = s.x * s.x + s.y * s.y + s.z * s.z + s.w * s.w;
    sq += __shfl_xor_sync(0xffffffffu, sq, 1);
    sq += __shfl_xor_sync(0xffffffffu, sq, 2);

    const float scale = sq / ((1.0f + sq) * (sqrtf(sq) + 1e-8f));
    s.x *= scale; s.y *= scale; s.z *= scale; s.w *= scale;

    __stcs(out + obase + t, s);
}

__global__ __launch_bounds__(256) void capsule_pool_squash_kernel(
    const float4* __restrict__ in, float4* __restrict__ out)
{
    __shared__ float4 sm0[1024];   // 16KB, unit 0
    __shared__ float4 sm1[1024];   // 16KB, unit 1

    const int t = threadIdx.x;
    const size_t ib0 = (size_t)blockIdx.x * 2048;          // unit 0 input
    const size_t ib1 = ib0 + 1024;                         // unit 1 input

    // ---- unit 0 loads (coalesced) ----
    float4 l0 = __ldcs(in + ib0 + t);
    float4 l1 = __ldcs(in + ib0 + t + 256);
    float4 l2 = __ldcs(in + ib0 + t + 512);
    float4 l3 = __ldcs(in + ib0 + t + 768);
    sm0[swz(t)]       = l0;
    sm0[swz(t + 256)] = l1;
    sm0[swz(t + 512)] = l2;
    sm0[swz(t + 768)] = l3;

    // ---- unit 1 loads issued BEFORE the sync: DRAM stays fed ----
    float4 m0 = __ldcs(in + ib1 + t);
    float4 m1 = __ldcs(in + ib1 + t + 256);
    float4 m2 = __ldcs(in + ib1 + t + 512);
    float4 m3 = __ldcs(in + ib1 + t + 768);

    __syncthreads();

    // ---- compute/store unit 0 while unit-1 loads are in flight ----
    pool_squash_store(sm0, out, (size_t)blockIdx.x * 512, t);

    // ---- stage unit 1 (separate buffer: no WAR hazard with sm0 reads) ----
    sm1[swz(t)]       = m0;
    sm1[swz(t + 256)] = m1;
    sm1[swz(t + 512)] = m2;
    sm1[swz(t + 768)] = m3;
    __syncthreads();

    pool_squash_store(sm1, out, (size_t)blockIdx.x * 512 + 256, t);
}

extern "C" void kernel_launch(void* const* d_in, const int* in_sizes, int n_in,
                              void* d_out, int out_size)
{
    const float4* in  = (const float4*)d_in[0];
    float4* out = (float4*)d_out;
    capsule_pool_squash_kernel<<<NBLOCKS, 256>>>(in, out);
}

// round 5
// speedup vs baseline: 1.0461x; 1.0461x over previous
#include <cuda_runtime.h>
#include <cuda_bf16.h>
#include <cstdint>

// CapsuleRoutingPooling, B=16 C=64 H=64 W=64 D=16, k=2.
// softmax over a length-1 axis => c==1 => routing loop is a no-op.
// out = squash( 2x2 sum-pool of D=16 vectors ).
//
// R5: shuffle-only, no smem, no __syncthreads.
// Thread t loads column t of all 4 H-rows of its unit (coalesced), so the
// dy-sums are thread-local and the dx-partner column (c^4) lives in lane^4
// of the SAME warp -> one shfl_xor(.,4) exchange replaces the whole smem
// round-trip. R4 showed occupancy is the chip-MLP multiplier here; this
// version spends ~30 regs, 0 smem, 0 barriers.

static constexpr int NBLOCKS = 16 * 64 * 16;   // 16384 units of 1024 float4

__device__ __forceinline__ float4 shfl_xor_f4(float4 v, int m) {
    float4 r;
    r.x = __shfl_xor_sync(0xffffffffu, v.x, m);
    r.y = __shfl_xor_sync(0xffffffffu, v.y, m);
    r.z = __shfl_xor_sync(0xffffffffu, v.z, m);
    r.w = __shfl_xor_sync(0xffffffffu, v.w, m);
    return r;
}

__global__ __launch_bounds__(256) void capsule_pool_squash_kernel(
    const float4* __restrict__ in, float4* __restrict__ out)
{
    const int t    = threadIdx.x;        // column within unit, 0..255
    const int lane = t & 31;

    const size_t ibase = (size_t)blockIdx.x * 1024;

    // Coalesced: column t of rows 0..3 of this unit.
    float4 l0 = __ldcs(in + ibase + t);          // row 0
    float4 l1 = __ldcs(in + ibase + t + 256);    // row 1
    float4 l2 = __ldcs(in + ibase + t + 512);    // row 2
    float4 l3 = __ldcs(in + ibase + t + 768);    // row 3

    // dy sums (thread-local).
    float4 v01, v23;
    v01.x = l0.x + l1.x;  v01.y = l0.y + l1.y;
    v01.z = l0.z + l1.z;  v01.w = l0.w + l1.w;
    v23.x = l2.x + l3.x;  v23.y = l2.y + l3.y;
    v23.z = l2.z + l3.z;  v23.w = l2.w + l3.w;

    // dx exchange with lane^4: send the half the partner needs, keep ours.
    // Lanes with (lane&4)==0 produce the nh_loc=0 output (from v01),
    // lanes with (lane&4)!=0 produce the nh_loc=1 output (from v23).
    const bool hi = (lane & 4) != 0;
    float4 send = hi ? v01 : v23;
    float4 keep = hi ? v23 : v01;
    float4 recv = shfl_xor_f4(send, 4);

    float4 s;
    s.x = keep.x + recv.x;
    s.y = keep.y + recv.y;
    s.z = keep.z + recv.z;
    s.w = keep.w + recv.w;

    // |s|^2 over D=16: butterfly across the 4-lane dq group.
    float sq = s.x * s.x + s.y * s.y + s.z * s.z + s.w * s.w;
    sq += __shfl_xor_sync(0xffffffffu, sq, 1);
    sq += __shfl_xor_sync(0xffffffffu, sq, 2);

    const float scale = sq / ((1.0f + sq) * (sqrtf(sq) + 1e-8f));
    s.x *= scale; s.y *= scale; s.z *= scale; s.w *= scale;

    // Output: unit holds 2 output rows of 128 float4 each.
    // col = t (0..255): nw = col>>3, dq = lane&3, nh_loc = hi.
    const int nw = t >> 3;
    const int dq = lane & 3;
    const size_t oidx = (size_t)blockIdx.x * 256
                      + (hi ? 128 : 0) + nw * 4 + dq;
    __stcs(out + oidx, s);
}

extern "C" void kernel_launch(void* const* d_in, const int* in_sizes, int n_in,
                              void* d_out, int out_size)
{
    const float4* in  = (const float4*)d_in[0];
    float4* out = (float4*)d_out;
    capsule_pool_squash_kernel<<<NBLOCKS, 256>>>(in, out);
}